// round 13
// baseline (speedup 1.0000x reference)
#include <cuda_runtime.h>
#include <cuda_bf16.h>
#include <cuda_fp16.h>
#include <cstdint>

// ============================ problem constants ============================
#define NROWS 65536
#define DDIM  512
#define KCL   1024

// fp8 scaling: x stored as e4m3(8*x), clusters as e4m3(64*c).
// accumulated cross = 512 * (x . c)  ->  2*cross = acc / 256.

// ============================ device scratch ===============================
__device__ uint8_t g_cf8[KCL * DDIM];          // clusters e4m3*64, row-major
// B pre-swizzled stage images: 32 blocks (nt*8+kcp) x 16384 bytes, each a
// [256 rows x 64B] smem-stage byte image (swizzle baked in).
__device__ uint8_t g_breord[32 * 16384];
__device__ float g_csq[KCL];                   // ||c||^2 (exact fp32)

// ============================ helpers ======================================
__device__ __forceinline__ uint32_t smem_to_u32(const void* p) {
    uint32_t a;
    asm("{ .reg .u64 t; cvta.to.shared.u64 t, %1; cvt.u32.u64 %0, t; }"
        : "=r"(a) : "l"(p));
    return a;
}

// pack 4 floats -> 4 e4m3 bytes (x0 in LSB)
__device__ __forceinline__ uint32_t pack_f8x4(float x0, float x1, float x2, float x3) {
    uint16_t lo, hi;
    asm("cvt.rn.satfinite.e4m3x2.f32 %0, %1, %2;" : "=h"(lo) : "f"(x1), "f"(x0));
    asm("cvt.rn.satfinite.e4m3x2.f32 %0, %1, %2;" : "=h"(hi) : "f"(x3), "f"(x2));
    return (uint32_t)lo | ((uint32_t)hi << 16);
}

// swizzled smem byte offset for (row, 16B-chunk) within a [rows x 64B] tile.
__device__ __forceinline__ uint32_t swz(uint32_t row, uint32_t chunk) {
    return (row << 6) + (((chunk) ^ ((row >> 1) & 3u)) << 4);
}

#define CP_ASYNC_16(saddr, gaddr) \
    asm volatile("cp.async.cg.shared.global [%0], [%1], 16;" \
                 :: "r"(saddr), "l"(gaddr))
#define CP_COMMIT() asm volatile("cp.async.commit_group;" ::: "memory")
#define CP_WAIT_2() asm volatile("cp.async.wait_group 2;" ::: "memory")
#define CP_WAIT_0() asm volatile("cp.async.wait_group 0;" ::: "memory")

#define LDSM_X4(r0, r1, r2, r3, addr) \
    asm volatile("ldmatrix.sync.aligned.m8n8.x4.shared.b16 {%0,%1,%2,%3}, [%4];" \
                 : "=r"(r0), "=r"(r1), "=r"(r2), "=r"(r3) : "r"(addr))

// fp8 e4m3 MMA: m16n8k32, FP16 accumulate (2 regs per fragment)
#define MMA_FP8H(d0, d1, a0, a1, a2, a3, b0, b1) \
    asm volatile("mma.sync.aligned.m16n8k32.row.col.f16.e4m3.e4m3.f16 " \
                 "{%0,%1}, {%2,%3,%4,%5}, {%6,%7}, {%0,%1};" \
                 : "+r"(d0), "+r"(d1) \
                 : "r"(a0), "r"(a1), "r"(a2), "r"(a3), "r"(b0), "r"(b1))

// ============================ prep kernels =================================
__global__ void prep_clusters(const float* __restrict__ cl) {
    int k = blockIdx.x;
    int t = threadIdx.x;  // 128 threads, one float4 each
    float4 v = reinterpret_cast<const float4*>(cl + (size_t)k * DDIM)[t];
    reinterpret_cast<uint32_t*>(g_cf8 + (size_t)k * DDIM)[t] =
        pack_f8x4(v.x * 64.f, v.y * 64.f, v.z * 64.f, v.w * 64.f);
    float s = v.x * v.x + v.y * v.y + v.z * v.z + v.w * v.w;
    for (int o = 16; o; o >>= 1) s += __shfl_down_sync(0xFFFFFFFFu, s, o);
    __shared__ float ps[4];
    if ((t & 31) == 0) ps[t >> 5] = s;
    __syncthreads();
    if (t == 0) g_csq[k] = ps[0] + ps[1] + ps[2] + ps[3];
}

// reorder g_cf8 into pre-swizzled stage images.
// Block (nt, kcp) = [256 rows x 64B] image of cluster rows [nt*256, nt*256+256)
// at K columns [kcp*64, kcp*64+64), SW-swizzled.
__global__ void prep_breord() {
    const int n = blockIdx.x;          // cluster row 0..1023
    const int t = threadIdx.x;         // 0..127, one uint32 (4 fp8 cols) each
    const int col = t * 4;
    const int nt  = n >> 8;            // 256-row tile
    const int r   = n & 255;
    const int kcp = col >> 6;          // 64-col window (0..7)
    const int ch  = (col & 63) >> 4;   // 16B chunk
    const int b   = col & 15;
    uint32_t v = reinterpret_cast<const uint32_t*>(g_cf8 + (size_t)n * DDIM)[t];
    uint8_t* dst = g_breord + (size_t)(nt * 8 + kcp) * 16384
                 + swz((uint32_t)r, (uint32_t)ch) + b;
    *reinterpret_cast<uint32_t*>(dst) = v;
}

// ============================ main kernel ==================================
// One CTA per 64-row block, 2 CTAs/SM. A (64x512 fp8, 32KB) smem-resident.
// 4 N-tiles of 256 cols; K-window = 64 fp8 (2 k32 mma steps, f16 accum).
// Warps 2(M) x 4(N), warp tile 32x64 (nj=8): MMA/LDSM ratio 2.67.
// B via 4-stage x 16KB ring of pre-swizzled LINEAR copies (slot = idx&3).
static constexpr int A_BYTES    = 64 * 512;                    // 32768
static constexpr int B_OFF      = A_BYTES;
static constexpr int B_STAGE    = 16384;                       // 256 rows x 64B
static constexpr int NSTAGE     = 4;
static constexpr int XSQ_OFF    = B_OFF + NSTAGE * B_STAGE;    // 98304 (64 f)
static constexpr int SMEM_TOTAL = XSQ_OFF + 256;               // 98560
// post-loop aliases into the dead B ring:
static constexpr int PS_OFF     = B_OFF;                       // [64][4] f
static constexpr int RSUM_OFF   = B_OFF + 1024;                // [64] f

__global__ void __launch_bounds__(256, 2)
cluster_main_kernel(const float* __restrict__ x, float* __restrict__ out) {
    extern __shared__ char smem[];
    const uint32_t sb = smem_to_u32(smem);
    const int t  = threadIdx.x;
    const int rowbase = blockIdx.x * 64;

    const int w  = t >> 5;                    // warp id
    const int l  = t & 31;                    // lane
    const int wm = w >> 2;                    // 0..1 (M, 32 rows)
    const int wn = w & 3;                     // 0..3 (N, 64 cols)
    const int group = l >> 2;                 // 0..7
    const int tid4  = l & 3;                  // 0..3

    float* xsq_s = reinterpret_cast<float*>(smem + XSQ_OFF);

    // ---- B loader: 4 linear 16B cp.asyncs (stage image copy) ----
    const uint32_t bdst = sb + B_OFF + t * 16;
    auto load_B = [&](int idx, int slot) {
        const uint8_t* gp = g_breord + (size_t)idx * 16384 + t * 16;
        const uint32_t s = bdst + slot * B_STAGE;
        CP_ASYNC_16(s,         (uint64_t)__cvta_generic_to_global(gp));
        CP_ASYNC_16(s + 4096,  (uint64_t)__cvta_generic_to_global(gp + 4096));
        CP_ASYNC_16(s + 8192,  (uint64_t)__cvta_generic_to_global(gp + 8192));
        CP_ASYNC_16(s + 12288, (uint64_t)__cvta_generic_to_global(gp + 12288));
    };

    // prologue: prefetch 3 stages, then convert A while they fly
    load_B(0, 0); CP_COMMIT();
    load_B(1, 1); CP_COMMIT();
    load_B(2, 2); CP_COMMIT();

    // ---- prologue: fp32 x -> e4m3(8x) smem A + exact x_sq (4 thr/row) ----
    {
        const int r  = t >> 2;             // local row 0..63
        const int cb = (t & 3) * 128;      // fp8-col base, 128 cols per thread
        const float* xr = x + (size_t)(rowbase + r) * DDIM + cb;
        float s = 0.f;
        #pragma unroll
        for (int i = 0; i < 8; ++i) {
            const int col = cb + i * 16;
            float4 f0 = reinterpret_cast<const float4*>(xr + i * 16)[0];
            float4 f1 = reinterpret_cast<const float4*>(xr + i * 16)[1];
            float4 f2 = reinterpret_cast<const float4*>(xr + i * 16)[2];
            float4 f3 = reinterpret_cast<const float4*>(xr + i * 16)[3];
            s += f0.x * f0.x + f0.y * f0.y + f0.z * f0.z + f0.w * f0.w
               + f1.x * f1.x + f1.y * f1.y + f1.z * f1.z + f1.w * f1.w
               + f2.x * f2.x + f2.y * f2.y + f2.z * f2.z + f2.w * f2.w
               + f3.x * f3.x + f3.y * f3.y + f3.z * f3.z + f3.w * f3.w;
            uint32_t p0 = pack_f8x4(f0.x * 8.f, f0.y * 8.f, f0.z * 8.f, f0.w * 8.f);
            uint32_t p1 = pack_f8x4(f1.x * 8.f, f1.y * 8.f, f1.z * 8.f, f1.w * 8.f);
            uint32_t p2 = pack_f8x4(f2.x * 8.f, f2.y * 8.f, f2.z * 8.f, f2.w * 8.f);
            uint32_t p3 = pack_f8x4(f3.x * 8.f, f3.y * 8.f, f3.z * 8.f, f3.w * 8.f);
            const int kc = col >> 6, j = (col & 63) >> 4;
            uint32_t dst = sb + kc * 4096 + swz((uint32_t)r, (uint32_t)j);
            asm volatile("st.shared.v4.b32 [%0], {%1, %2, %3, %4};"
                         :: "r"(dst), "r"(p0), "r"(p1), "r"(p2), "r"(p3));
        }
        s += __shfl_xor_sync(0xFFFFFFFFu, s, 1);
        s += __shfl_xor_sync(0xFFFFFFFFu, s, 2);
        if (tid4 == 0) xsq_s[r] = s;
    }
    __syncthreads();

    // this thread's row squared-norms, in registers for all epilogues
    const int er0 = wm * 32 + group;
    float xs[2][2];
    #pragma unroll
    for (int mi = 0; mi < 2; ++mi) {
        xs[mi][0] = xsq_s[er0 + mi * 16];
        xs[mi][1] = xsq_s[er0 + mi * 16 + 8];
    }

    // ---- ldmatrix lane offsets ----
    uint32_t aAddr[2][2];
    {
        int r8   = (l & 7) + (((l >> 3) & 1) << 3);
        int cbit = l >> 4;
        #pragma unroll
        for (int mi = 0; mi < 2; ++mi) {
            int row = wm * 32 + mi * 16 + r8;
            aAddr[mi][0] = swz(row, cbit);
            aAddr[mi][1] = swz(row, 2 + cbit);
        }
    }
    // B: 4 LDSM_X4 groups p=0..3 covering nj = 2p + (m>>1), k-half = m&1
    uint32_t bAddr[4][2];
    {
        int m = l >> 3;
        #pragma unroll
        for (int p = 0; p < 4; ++p) {
            int row = wn * 64 + (p * 2 + (m >> 1)) * 8 + (l & 7);
            #pragma unroll
            for (int ks = 0; ks < 2; ++ks)
                bAddr[p][ks] = swz(row, 2 * ks + (m & 1));
        }
    }

    // fp16 accumulators: 2 regs per (mi,nj) fragment
    uint32_t acc[2][8][2];
    #pragma unroll
    for (int mi = 0; mi < 2; ++mi)
        #pragma unroll
        for (int nj = 0; nj < 8; ++nj) { acc[mi][nj][0] = 0u; acc[mi][nj][1] = 0u; }

    float rs[2][2] = {{0.f, 0.f}, {0.f, 0.f}};   // running row sums

    // precomputed output row pointers
    float* outp[2][2];
    #pragma unroll
    for (int mi = 0; mi < 2; ++mi) {
        const int r0 = wm * 32 + mi * 16 + group;
        outp[mi][0] = out + (size_t)(rowbase + r0) * KCL;
        outp[mi][1] = out + (size_t)(rowbase + r0 + 8) * KCL;
    }

    // ---- 4 N-tiles x 8 K-windows of 64; slot = idx&3 (compile-time) ----
    #pragma unroll 1
    for (int nt = 0; nt < 4; ++nt) {
        #pragma unroll
        for (int kcp = 0; kcp < 8; ++kcp) {
            const int idx = nt * 8 + kcp;
            CP_WAIT_2();
            __syncthreads();
            if (idx + 3 < 32) load_B(idx + 3, (kcp + 3) & 3);
            CP_COMMIT();

            const uint32_t sA  = sb + kcp * 4096;
            const uint32_t sBs = sb + B_OFF + (kcp & 3) * B_STAGE;
            #pragma unroll
            for (int ks = 0; ks < 2; ++ks) {
                uint32_t a[2][4], b[8][2];
                #pragma unroll
                for (int mi = 0; mi < 2; ++mi)
                    LDSM_X4(a[mi][0], a[mi][1], a[mi][2], a[mi][3], sA + aAddr[mi][ks]);
                #pragma unroll
                for (int p = 0; p < 4; ++p)
                    LDSM_X4(b[2*p][0], b[2*p][1], b[2*p+1][0], b[2*p+1][1],
                            sBs + bAddr[p][ks]);
                #pragma unroll
                for (int mi = 0; mi < 2; ++mi)
                    #pragma unroll
                    for (int nj = 0; nj < 8; ++nj)
                        MMA_FP8H(acc[mi][nj][0], acc[mi][nj][1],
                                 a[mi][0], a[mi][1], a[mi][2], a[mi][3],
                                 b[nj][0], b[nj][1]);
            }
        }

        // ---- N-tile epilogue (unpack f16 acc; csq via __ldg) ----
        {
            const int ntbase = nt * 256;
            const float kk = 1.f / 256.f;   // 2*cross = acc/256
            #pragma unroll
            for (int mi = 0; mi < 2; ++mi) {
                #pragma unroll
                for (int nj = 0; nj < 8; ++nj) {
                    const int colg = ntbase + wn * 64 + nj * 8 + tid4 * 2;
                    const float cs0 = __ldg(g_csq + colg);
                    const float cs1 = __ldg(g_csq + colg + 1);
                    float2 f0 = __half22float2(*reinterpret_cast<__half2*>(&acc[mi][nj][0]));
                    float2 f1 = __half22float2(*reinterpret_cast<__half2*>(&acc[mi][nj][1]));
                    acc[mi][nj][0] = 0u; acc[mi][nj][1] = 0u;
                    float q00 = __fdividef(1.f, 1.f + fmaxf(xs[mi][0] + cs0 - kk * f0.x, 0.f));
                    float q01 = __fdividef(1.f, 1.f + fmaxf(xs[mi][0] + cs1 - kk * f0.y, 0.f));
                    float q10 = __fdividef(1.f, 1.f + fmaxf(xs[mi][1] + cs0 - kk * f1.x, 0.f));
                    float q11 = __fdividef(1.f, 1.f + fmaxf(xs[mi][1] + cs1 - kk * f1.y, 0.f));
                    rs[mi][0] += q00 + q01;
                    rs[mi][1] += q10 + q11;
                    *reinterpret_cast<float2*>(outp[mi][0] + colg) = make_float2(q00, q01);
                    *reinterpret_cast<float2*>(outp[mi][1] + colg) = make_float2(q10, q11);
                }
            }
        }
    }

    // ---- final row-sum reduction (ps/rsum alias the dead B ring) ----
    CP_WAIT_0();
    __syncthreads();
    float* ps     = reinterpret_cast<float*>(smem + PS_OFF);   // [64][4]
    float* rsum_s = reinterpret_cast<float*>(smem + RSUM_OFF); // [64]
    #pragma unroll
    for (int mi = 0; mi < 2; ++mi) {
        float s0 = rs[mi][0], s1 = rs[mi][1];
        s0 += __shfl_xor_sync(0xFFFFFFFFu, s0, 1);
        s0 += __shfl_xor_sync(0xFFFFFFFFu, s0, 2);
        s1 += __shfl_xor_sync(0xFFFFFFFFu, s1, 1);
        s1 += __shfl_xor_sync(0xFFFFFFFFu, s1, 2);
        if (tid4 == 0) {
            const int r0 = wm * 32 + mi * 16 + group;
            ps[r0 * 4 + wn] = s0;
            ps[(r0 + 8) * 4 + wn] = s1;
        }
    }
    __syncthreads();
    if (t < 64)
        rsum_s[t] = __fdividef(1.f, ps[t * 4 + 0] + ps[t * 4 + 1] +
                                    ps[t * 4 + 2] + ps[t * 4 + 3]);
    __syncthreads();

    // ---- fused renormalization (256KB output slab, L2-resident) ----
    float4* op = reinterpret_cast<float4*>(out + (size_t)rowbase * KCL);
    #pragma unroll 4
    for (int r = 0; r < 64; ++r) {
        float iv = rsum_s[r];
        float4 v = op[(size_t)r * 256 + t];
        v.x *= iv; v.y *= iv; v.z *= iv; v.w *= iv;
        op[(size_t)r * 256 + t] = v;
    }
}

// ============================ launch =======================================
extern "C" void kernel_launch(void* const* d_in, const int* in_sizes, int n_in,
                              void* d_out, int out_size) {
    const float* x  = (const float*)d_in[0];   // (65536, 512)
    const float* cl = (const float*)d_in[1];   // (1024, 512)
    float* out = (float*)d_out;                // (65536, 1024)
    (void)in_sizes; (void)n_in; (void)out_size;

    cudaFuncSetAttribute(cluster_main_kernel,
                         cudaFuncAttributeMaxDynamicSharedMemorySize, SMEM_TOTAL);

    prep_clusters<<<KCL, 128>>>(cl);
    prep_breord<<<KCL, 128>>>();
    cluster_main_kernel<<<NROWS / 64, 256, SMEM_TOTAL>>>(x, out);
}

// round 14
// speedup vs baseline: 1.0841x; 1.0841x over previous
#include <cuda_runtime.h>
#include <cuda_bf16.h>
#include <cuda_fp16.h>
#include <cstdint>

// ============================ problem constants ============================
#define NROWS 65536
#define DDIM  512
#define KCL   1024

// fp8 scaling: x stored as e4m3(8*x), clusters as e4m3(64*c).
// accumulated cross = 512 * (x . c)  ->  2*cross = acc / 256.

// ============================ device scratch ===============================
__device__ uint8_t g_cf8[KCL * DDIM];          // clusters e4m3*64, row-major
// B pre-swizzled stage images: 32 blocks (nt*4+kcp) x 16384 bytes, each a
// [128 rows x 128B] smem-stage byte image (sub-chunk + swizzle baked in).
__device__ uint8_t g_breord[32 * 16384];
__device__ float g_csq[KCL];                   // ||c||^2 (exact fp32)

// ============================ helpers ======================================
__device__ __forceinline__ uint32_t smem_to_u32(const void* p) {
    uint32_t a;
    asm("{ .reg .u64 t; cvta.to.shared.u64 t, %1; cvt.u32.u64 %0, t; }"
        : "=r"(a) : "l"(p));
    return a;
}

// pack 4 floats -> 4 e4m3 bytes (x0 in LSB)
__device__ __forceinline__ uint32_t pack_f8x4(float x0, float x1, float x2, float x3) {
    uint16_t lo, hi;
    asm("cvt.rn.satfinite.e4m3x2.f32 %0, %1, %2;" : "=h"(lo) : "f"(x1), "f"(x0));
    asm("cvt.rn.satfinite.e4m3x2.f32 %0, %1, %2;" : "=h"(hi) : "f"(x3), "f"(x2));
    return (uint32_t)lo | ((uint32_t)hi << 16);
}

// swizzled smem byte offset for (row, 16B-chunk) within a [rows x 64B] tile.
__device__ __forceinline__ uint32_t swz(uint32_t row, uint32_t chunk) {
    return (row << 6) + (((chunk) ^ ((row >> 1) & 3u)) << 4);
}

#define CP_ASYNC_16(saddr, gaddr) \
    asm volatile("cp.async.cg.shared.global [%0], [%1], 16;" \
                 :: "r"(saddr), "l"(gaddr))
#define CP_COMMIT() asm volatile("cp.async.commit_group;" ::: "memory")
#define CP_WAIT_1() asm volatile("cp.async.wait_group 1;" ::: "memory")
#define CP_WAIT_0() asm volatile("cp.async.wait_group 0;" ::: "memory")

#define LDSM_X4(r0, r1, r2, r3, addr) \
    asm volatile("ldmatrix.sync.aligned.m8n8.x4.shared.b16 {%0,%1,%2,%3}, [%4];" \
                 : "=r"(r0), "=r"(r1), "=r"(r2), "=r"(r3) : "r"(addr))

// fp8 e4m3 MMA: m16n8k32, FP16 accumulate (2 regs per fragment)
#define MMA_FP8H(d0, d1, a0, a1, a2, a3, b0, b1) \
    asm volatile("mma.sync.aligned.m16n8k32.row.col.f16.e4m3.e4m3.f16 " \
                 "{%0,%1}, {%2,%3,%4,%5}, {%6,%7}, {%0,%1};" \
                 : "+r"(d0), "+r"(d1) \
                 : "r"(a0), "r"(a1), "r"(a2), "r"(a3), "r"(b0), "r"(b1))

// ============================ prep kernels =================================
__global__ void prep_clusters(const float* __restrict__ cl) {
    int k = blockIdx.x;
    int t = threadIdx.x;  // 128 threads, one float4 each
    float4 v = reinterpret_cast<const float4*>(cl + (size_t)k * DDIM)[t];
    reinterpret_cast<uint32_t*>(g_cf8 + (size_t)k * DDIM)[t] =
        pack_f8x4(v.x * 64.f, v.y * 64.f, v.z * 64.f, v.w * 64.f);
    float s = v.x * v.x + v.y * v.y + v.z * v.z + v.w * v.w;
    for (int o = 16; o; o >>= 1) s += __shfl_down_sync(0xFFFFFFFFu, s, o);
    __shared__ float ps[4];
    if ((t & 31) == 0) ps[t >> 5] = s;
    __syncthreads();
    if (t == 0) g_csq[k] = ps[0] + ps[1] + ps[2] + ps[3];
}

// reorder g_cf8 into pre-swizzled stage images (one uint32 per thread).
// Block (nt, kcp) = [128 rows x 128B] image of cluster rows [nt*128, ..+128)
// at K columns [kcp*128, ..+128), split into 2 x 64B sub-chunks, swizzled.
__global__ void prep_breord() {
    const int n = blockIdx.x;          // cluster row 0..1023
    const int t = threadIdx.x;         // 0..127, 4 fp8 cols each
    const int col = t * 4;
    const int nt  = n >> 7;
    const int r   = n & 127;
    const int kcp = col >> 7;
    const int s   = (col & 127) >> 6;
    const int ch  = (col & 63) >> 4;
    const int b   = col & 15;
    uint32_t v = reinterpret_cast<const uint32_t*>(g_cf8 + (size_t)n * DDIM)[t];
    uint8_t* dst = g_breord + (size_t)(nt * 4 + kcp) * 16384
                 + s * 8192 + swz((uint32_t)r, (uint32_t)ch) + b;
    *reinterpret_cast<uint32_t*>(dst) = v;
}

// ============================ main kernel ==================================
// One CTA per 64-row block, 3 CTAs/SM (24 warps/SM). A (64x512 fp8, 32KB)
// smem-resident. 8 N-tiles of 128 cols; K-window = 128 fp8 (4 k32 steps,
// f16 accum). B via DOUBLE-buffered 16KB stages of pre-swizzled linear
// copies (slot = idx&1, compile-time). Prefetch distance 1 window.
static constexpr int A_BYTES    = 64 * 512;                    // 32768
static constexpr int B_OFF      = A_BYTES;
static constexpr int B_STAGE    = 16384;
static constexpr int NSTAGE     = 2;
static constexpr int XSQ_OFF    = B_OFF + NSTAGE * B_STAGE;    // 65536 (64 f)
static constexpr int SMEM_TOTAL = XSQ_OFF + 256;               // 65792
// post-loop aliases into the dead B ring:
static constexpr int PS_OFF     = B_OFF;                       // [64][4] f
static constexpr int RSUM_OFF   = B_OFF + 1024;                // [64] f

__global__ void __launch_bounds__(256, 3)
cluster_main_kernel(const float* __restrict__ x, float* __restrict__ out) {
    extern __shared__ char smem[];
    const uint32_t sb = smem_to_u32(smem);
    const int t  = threadIdx.x;
    const int rowbase = blockIdx.x * 64;

    const int w  = t >> 5;                    // warp id
    const int l  = t & 31;                    // lane
    const int wm = w >> 2;                    // 0..1 (M, 32 rows)
    const int wn = w & 3;                     // 0..3 (N, 32 cols)
    const int group = l >> 2;                 // 0..7
    const int tid4  = l & 3;                  // 0..3

    float* xsq_s = reinterpret_cast<float*>(smem + XSQ_OFF);

    // ---- B loader: 4 linear 16B cp.asyncs (stage image copy) ----
    const uint32_t bdst = sb + B_OFF + t * 16;
    auto load_B = [&](int idx, int slot) {
        const uint8_t* gp = g_breord + (size_t)idx * 16384 + t * 16;
        const uint32_t s = bdst + slot * B_STAGE;
        CP_ASYNC_16(s,         (uint64_t)__cvta_generic_to_global(gp));
        CP_ASYNC_16(s + 4096,  (uint64_t)__cvta_generic_to_global(gp + 4096));
        CP_ASYNC_16(s + 8192,  (uint64_t)__cvta_generic_to_global(gp + 8192));
        CP_ASYNC_16(s + 12288, (uint64_t)__cvta_generic_to_global(gp + 12288));
    };

    // prologue: fill both buffers, then convert A while they fly
    load_B(0, 0); CP_COMMIT();
    load_B(1, 1); CP_COMMIT();

    // ---- prologue: fp32 x -> e4m3(8x) smem A + exact x_sq (4 thr/row) ----
    {
        const int r  = t >> 2;             // local row 0..63
        const int cb = (t & 3) * 128;      // fp8-col base, 128 cols per thread
        const float* xr = x + (size_t)(rowbase + r) * DDIM + cb;
        float s = 0.f;
        #pragma unroll
        for (int i = 0; i < 8; ++i) {
            const int col = cb + i * 16;
            float4 f0 = reinterpret_cast<const float4*>(xr + i * 16)[0];
            float4 f1 = reinterpret_cast<const float4*>(xr + i * 16)[1];
            float4 f2 = reinterpret_cast<const float4*>(xr + i * 16)[2];
            float4 f3 = reinterpret_cast<const float4*>(xr + i * 16)[3];
            s += f0.x * f0.x + f0.y * f0.y + f0.z * f0.z + f0.w * f0.w
               + f1.x * f1.x + f1.y * f1.y + f1.z * f1.z + f1.w * f1.w
               + f2.x * f2.x + f2.y * f2.y + f2.z * f2.z + f2.w * f2.w
               + f3.x * f3.x + f3.y * f3.y + f3.z * f3.z + f3.w * f3.w;
            uint32_t p0 = pack_f8x4(f0.x * 8.f, f0.y * 8.f, f0.z * 8.f, f0.w * 8.f);
            uint32_t p1 = pack_f8x4(f1.x * 8.f, f1.y * 8.f, f1.z * 8.f, f1.w * 8.f);
            uint32_t p2 = pack_f8x4(f2.x * 8.f, f2.y * 8.f, f2.z * 8.f, f2.w * 8.f);
            uint32_t p3 = pack_f8x4(f3.x * 8.f, f3.y * 8.f, f3.z * 8.f, f3.w * 8.f);
            const int kc = col >> 6, j = (col & 63) >> 4;
            uint32_t dst = sb + kc * 4096 + swz((uint32_t)r, (uint32_t)j);
            asm volatile("st.shared.v4.b32 [%0], {%1, %2, %3, %4};"
                         :: "r"(dst), "r"(p0), "r"(p1), "r"(p2), "r"(p3));
        }
        s += __shfl_xor_sync(0xFFFFFFFFu, s, 1);
        s += __shfl_xor_sync(0xFFFFFFFFu, s, 2);
        if (tid4 == 0) xsq_s[r] = s;
    }
    __syncthreads();

    // this thread's row squared-norms, in registers for all epilogues
    const int er0 = wm * 32 + group;
    float xs[2][2];
    #pragma unroll
    for (int mi = 0; mi < 2; ++mi) {
        xs[mi][0] = xsq_s[er0 + mi * 16];
        xs[mi][1] = xsq_s[er0 + mi * 16 + 8];
    }

    // ---- ldmatrix lane offsets ----
    uint32_t aAddr[2][2];
    {
        int r8   = (l & 7) + (((l >> 3) & 1) << 3);
        int cbit = l >> 4;
        #pragma unroll
        for (int mi = 0; mi < 2; ++mi) {
            int row = wm * 32 + mi * 16 + r8;
            aAddr[mi][0] = swz(row, cbit);
            aAddr[mi][1] = swz(row, 2 + cbit);
        }
    }
    uint32_t bAddr[2][2];
    {
        int m = l >> 3;
        #pragma unroll
        for (int p = 0; p < 2; ++p) {
            int row = wn * 32 + (p * 2 + (m >> 1)) * 8 + (l & 7);
            #pragma unroll
            for (int ks = 0; ks < 2; ++ks)
                bAddr[p][ks] = swz(row, 2 * ks + (m & 1));
        }
    }

    // fp16 accumulators: 2 regs per (mi,nj) fragment
    uint32_t acc[2][4][2];
    #pragma unroll
    for (int mi = 0; mi < 2; ++mi)
        #pragma unroll
        for (int nj = 0; nj < 4; ++nj) { acc[mi][nj][0] = 0u; acc[mi][nj][1] = 0u; }

    float rs[2][2] = {{0.f, 0.f}, {0.f, 0.f}};   // running row sums

    // ---- 8 N-tiles x 4 K-windows of 128; slot = idx&1 = kcp&1 ----
    #pragma unroll 1
    for (int nt = 0; nt < 8; ++nt) {
        #pragma unroll
        for (int kcp = 0; kcp < 4; ++kcp) {
            const int idx = nt * 4 + kcp;
            CP_WAIT_0();
            __syncthreads();
            if (idx >= 1 && idx + 1 < 32) load_B(idx + 1, (kcp + 1) & 1);
            CP_COMMIT();

            const uint32_t stg = sb + B_OFF + (kcp & 1) * B_STAGE;
            #pragma unroll
            for (int half = 0; half < 2; ++half) {
                const uint32_t sA = sb + (kcp * 2 + half) * 4096;
                const uint32_t sB = stg + half * 8192;
                #pragma unroll
                for (int ks = 0; ks < 2; ++ks) {
                    uint32_t a[2][4], b[4][2];
                    #pragma unroll
                    for (int mi = 0; mi < 2; ++mi)
                        LDSM_X4(a[mi][0], a[mi][1], a[mi][2], a[mi][3], sA + aAddr[mi][ks]);
                    #pragma unroll
                    for (int p = 0; p < 2; ++p)
                        LDSM_X4(b[2*p][0], b[2*p][1], b[2*p+1][0], b[2*p+1][1],
                                sB + bAddr[p][ks]);
                    #pragma unroll
                    for (int mi = 0; mi < 2; ++mi)
                        #pragma unroll
                        for (int nj = 0; nj < 4; ++nj)
                            MMA_FP8H(acc[mi][nj][0], acc[mi][nj][1],
                                     a[mi][0], a[mi][1], a[mi][2], a[mi][3],
                                     b[nj][0], b[nj][1]);
                }
            }
        }

        // ---- N-tile epilogue (unpack f16 acc; csq via __ldg) ----
        {
            const int ntbase = nt * 128;
            const float kk = 1.f / 256.f;   // 2*cross = acc/256
            #pragma unroll
            for (int mi = 0; mi < 2; ++mi) {
                const int r0 = wm * 32 + mi * 16 + group;
                float* o0 = out + (size_t)(rowbase + r0) * KCL;
                float* o1 = out + (size_t)(rowbase + r0 + 8) * KCL;
                #pragma unroll
                for (int nj = 0; nj < 4; ++nj) {
                    const int colg = ntbase + wn * 32 + nj * 8 + tid4 * 2;
                    const float cs0 = __ldg(g_csq + colg);
                    const float cs1 = __ldg(g_csq + colg + 1);
                    float2 f0 = __half22float2(*reinterpret_cast<__half2*>(&acc[mi][nj][0]));
                    float2 f1 = __half22float2(*reinterpret_cast<__half2*>(&acc[mi][nj][1]));
                    acc[mi][nj][0] = 0u; acc[mi][nj][1] = 0u;
                    float q00 = __fdividef(1.f, 1.f + fmaxf(xs[mi][0] + cs0 - kk * f0.x, 0.f));
                    float q01 = __fdividef(1.f, 1.f + fmaxf(xs[mi][0] + cs1 - kk * f0.y, 0.f));
                    float q10 = __fdividef(1.f, 1.f + fmaxf(xs[mi][1] + cs0 - kk * f1.x, 0.f));
                    float q11 = __fdividef(1.f, 1.f + fmaxf(xs[mi][1] + cs1 - kk * f1.y, 0.f));
                    rs[mi][0] += q00 + q01;
                    rs[mi][1] += q10 + q11;
                    *reinterpret_cast<float2*>(o0 + colg) = make_float2(q00, q01);
                    *reinterpret_cast<float2*>(o1 + colg) = make_float2(q10, q11);
                }
            }
        }
    }

    // ---- final row-sum reduction (ps/rsum alias the dead B ring) ----
    CP_WAIT_0();
    __syncthreads();
    float* ps     = reinterpret_cast<float*>(smem + PS_OFF);   // [64][4]
    float* rsum_s = reinterpret_cast<float*>(smem + RSUM_OFF); // [64]
    #pragma unroll
    for (int mi = 0; mi < 2; ++mi) {
        float s0 = rs[mi][0], s1 = rs[mi][1];
        s0 += __shfl_xor_sync(0xFFFFFFFFu, s0, 1);
        s0 += __shfl_xor_sync(0xFFFFFFFFu, s0, 2);
        s1 += __shfl_xor_sync(0xFFFFFFFFu, s1, 1);
        s1 += __shfl_xor_sync(0xFFFFFFFFu, s1, 2);
        if (tid4 == 0) {
            const int r0 = wm * 32 + mi * 16 + group;
            ps[r0 * 4 + wn] = s0;
            ps[(r0 + 8) * 4 + wn] = s1;
        }
    }
    __syncthreads();
    if (t < 64)
        rsum_s[t] = __fdividef(1.f, ps[t * 4 + 0] + ps[t * 4 + 1] +
                                    ps[t * 4 + 2] + ps[t * 4 + 3]);
    __syncthreads();

    // ---- fused renormalization (256KB output slab, L2-resident) ----
    float4* op = reinterpret_cast<float4*>(out + (size_t)rowbase * KCL);
    #pragma unroll 4
    for (int r = 0; r < 64; ++r) {
        float iv = rsum_s[r];
        float4 v = op[(size_t)r * 256 + t];
        v.x *= iv; v.y *= iv; v.z *= iv; v.w *= iv;
        op[(size_t)r * 256 + t] = v;
    }
}

// ============================ launch =======================================
extern "C" void kernel_launch(void* const* d_in, const int* in_sizes, int n_in,
                              void* d_out, int out_size) {
    const float* x  = (const float*)d_in[0];   // (65536, 512)
    const float* cl = (const float*)d_in[1];   // (1024, 512)
    float* out = (float*)d_out;                // (65536, 1024)
    (void)in_sizes; (void)n_in; (void)out_size;

    cudaFuncSetAttribute(cluster_main_kernel,
                         cudaFuncAttributeMaxDynamicSharedMemorySize, SMEM_TOTAL);

    prep_clusters<<<KCL, 128>>>(cl);
    prep_breord<<<KCL, 128>>>();
    cluster_main_kernel<<<NROWS / 64, 256, SMEM_TOTAL>>>(x, out);
}

// round 15
// speedup vs baseline: 1.0915x; 1.0068x over previous
#include <cuda_runtime.h>
#include <cuda_bf16.h>
#include <cuda_fp16.h>
#include <cstdint>

// ============================ problem constants ============================
#define NROWS 65536
#define DDIM  512
#define KCL   1024

// fp8 scaling: x stored as e4m3(8*x), clusters as e4m3(64*c).
// accumulated cross = 512 * (x . c)  ->  2*cross = acc / 256.

// ============================ device scratch ===============================
// B pre-swizzled stage images: 32 blocks (nt*4+kcp) x 16384 bytes, each a
// [128 rows x 128B] smem-stage byte image (sub-chunk + swizzle baked in).
__device__ uint8_t g_breord[32 * 16384];
__device__ float g_csq[KCL];                   // ||c||^2 (exact fp32)

// ============================ helpers ======================================
__device__ __forceinline__ uint32_t smem_to_u32(const void* p) {
    uint32_t a;
    asm("{ .reg .u64 t; cvta.to.shared.u64 t, %1; cvt.u32.u64 %0, t; }"
        : "=r"(a) : "l"(p));
    return a;
}

// pack 4 floats -> 4 e4m3 bytes (x0 in LSB)
__device__ __forceinline__ uint32_t pack_f8x4(float x0, float x1, float x2, float x3) {
    uint16_t lo, hi;
    asm("cvt.rn.satfinite.e4m3x2.f32 %0, %1, %2;" : "=h"(lo) : "f"(x1), "f"(x0));
    asm("cvt.rn.satfinite.e4m3x2.f32 %0, %1, %2;" : "=h"(hi) : "f"(x3), "f"(x2));
    return (uint32_t)lo | ((uint32_t)hi << 16);
}

// swizzled smem byte offset for (row, 16B-chunk) within a [rows x 64B] tile.
__device__ __forceinline__ uint32_t swz(uint32_t row, uint32_t chunk) {
    return (row << 6) + (((chunk) ^ ((row >> 1) & 3u)) << 4);
}

#define CP_ASYNC_16(saddr, gaddr) \
    asm volatile("cp.async.cg.shared.global [%0], [%1], 16;" \
                 :: "r"(saddr), "l"(gaddr))
#define CP_COMMIT() asm volatile("cp.async.commit_group;" ::: "memory")
#define CP_WAIT_1() asm volatile("cp.async.wait_group 1;" ::: "memory")
#define CP_WAIT_0() asm volatile("cp.async.wait_group 0;" ::: "memory")

#define LDSM_X4(r0, r1, r2, r3, addr) \
    asm volatile("ldmatrix.sync.aligned.m8n8.x4.shared.b16 {%0,%1,%2,%3}, [%4];" \
                 : "=r"(r0), "=r"(r1), "=r"(r2), "=r"(r3) : "r"(addr))

// fp8 e4m3 MMA: m16n8k32, FP16 accumulate (2 regs per fragment)
#define MMA_FP8H(d0, d1, a0, a1, a2, a3, b0, b1) \
    asm volatile("mma.sync.aligned.m16n8k32.row.col.f16.e4m3.e4m3.f16 " \
                 "{%0,%1}, {%2,%3,%4,%5}, {%6,%7}, {%0,%1};" \
                 : "+r"(d0), "+r"(d1) \
                 : "r"(a0), "r"(a1), "r"(a2), "r"(a3), "r"(b0), "r"(b1))

// ============================ prep kernel ==================================
// Single pass: clusters fp32 -> e4m3(64*c) written DIRECTLY into the
// pre-swizzled stage-image layout, plus exact ||c||^2.
__global__ void prep_clusters(const float* __restrict__ cl) {
    const int n = blockIdx.x;          // cluster row 0..1023
    const int t = threadIdx.x;         // 0..127, 4 fp8 cols each
    float4 v = reinterpret_cast<const float4*>(cl + (size_t)n * DDIM)[t];
    uint32_t pk = pack_f8x4(v.x * 64.f, v.y * 64.f, v.z * 64.f, v.w * 64.f);

    const int col = t * 4;
    const int nt  = n >> 7;            // 128-row tile
    const int r   = n & 127;
    const int kcp = col >> 7;          // 128-K window
    const int s   = (col & 127) >> 6;  // 64B sub-chunk
    const int ch  = (col & 63) >> 4;   // 16B chunk
    const int b   = col & 15;
    uint8_t* dst = g_breord + (size_t)(nt * 4 + kcp) * 16384
                 + s * 8192 + swz((uint32_t)r, (uint32_t)ch) + b;
    *reinterpret_cast<uint32_t*>(dst) = pk;

    float sum = v.x * v.x + v.y * v.y + v.z * v.z + v.w * v.w;
    for (int o = 16; o; o >>= 1) sum += __shfl_down_sync(0xFFFFFFFFu, sum, o);
    __shared__ float ps[4];
    if ((t & 31) == 0) ps[t >> 5] = sum;
    __syncthreads();
    if (t == 0) g_csq[n] = ps[0] + ps[1] + ps[2] + ps[3];
}

// ============================ main kernel ==================================
// One CTA per 64-row block, 3 CTAs/SM (24 warps/SM). A (64x512 fp8, 32KB)
// smem-resident. 8 N-tiles of 128 cols; K-window = 128 fp8 (4 k32 steps,
// f16 accum). B via DOUBLE-buffered 16KB stages of pre-swizzled linear
// copies (slot = idx&1, compile-time). Prefetch distance 1 window.
static constexpr int A_BYTES    = 64 * 512;                    // 32768
static constexpr int B_OFF      = A_BYTES;
static constexpr int B_STAGE    = 16384;
static constexpr int NSTAGE     = 2;
static constexpr int XSQ_OFF    = B_OFF + NSTAGE * B_STAGE;    // 65536 (64 f)
static constexpr int SMEM_TOTAL = XSQ_OFF + 256;               // 65792
// post-loop aliases into the dead B ring:
static constexpr int PS_OFF     = B_OFF;                       // [64][4] f
static constexpr int RSUM_OFF   = B_OFF + 1024;                // [64] f

__global__ void __launch_bounds__(256, 3)
cluster_main_kernel(const float* __restrict__ x, float* __restrict__ out) {
    extern __shared__ char smem[];
    const uint32_t sb = smem_to_u32(smem);
    const int t  = threadIdx.x;
    const int rowbase = blockIdx.x * 64;

    const int w  = t >> 5;                    // warp id
    const int l  = t & 31;                    // lane
    const int wm = w >> 2;                    // 0..1 (M, 32 rows)
    const int wn = w & 3;                     // 0..3 (N, 32 cols)
    const int group = l >> 2;                 // 0..7
    const int tid4  = l & 3;                  // 0..3

    float* xsq_s = reinterpret_cast<float*>(smem + XSQ_OFF);

    // ---- B loader: 4 linear 16B cp.asyncs (stage image copy) ----
    const uint32_t bdst = sb + B_OFF + t * 16;
    auto load_B = [&](int idx, int slot) {
        const uint8_t* gp = g_breord + (size_t)idx * 16384 + t * 16;
        const uint32_t s = bdst + slot * B_STAGE;
        CP_ASYNC_16(s,         (uint64_t)__cvta_generic_to_global(gp));
        CP_ASYNC_16(s + 4096,  (uint64_t)__cvta_generic_to_global(gp + 4096));
        CP_ASYNC_16(s + 8192,  (uint64_t)__cvta_generic_to_global(gp + 8192));
        CP_ASYNC_16(s + 12288, (uint64_t)__cvta_generic_to_global(gp + 12288));
    };

    // prologue: fill both buffers, then convert A while they fly
    load_B(0, 0); CP_COMMIT();
    load_B(1, 1); CP_COMMIT();

    // ---- prologue: fp32 x -> e4m3(8x) smem A + exact x_sq (4 thr/row) ----
    {
        const int r  = t >> 2;             // local row 0..63
        const int cb = (t & 3) * 128;      // fp8-col base, 128 cols per thread
        const float* xr = x + (size_t)(rowbase + r) * DDIM + cb;
        float s = 0.f;
        #pragma unroll
        for (int i = 0; i < 8; ++i) {
            const int col = cb + i * 16;
            float4 f0 = reinterpret_cast<const float4*>(xr + i * 16)[0];
            float4 f1 = reinterpret_cast<const float4*>(xr + i * 16)[1];
            float4 f2 = reinterpret_cast<const float4*>(xr + i * 16)[2];
            float4 f3 = reinterpret_cast<const float4*>(xr + i * 16)[3];
            s += f0.x * f0.x + f0.y * f0.y + f0.z * f0.z + f0.w * f0.w
               + f1.x * f1.x + f1.y * f1.y + f1.z * f1.z + f1.w * f1.w
               + f2.x * f2.x + f2.y * f2.y + f2.z * f2.z + f2.w * f2.w
               + f3.x * f3.x + f3.y * f3.y + f3.z * f3.z + f3.w * f3.w;
            uint32_t p0 = pack_f8x4(f0.x * 8.f, f0.y * 8.f, f0.z * 8.f, f0.w * 8.f);
            uint32_t p1 = pack_f8x4(f1.x * 8.f, f1.y * 8.f, f1.z * 8.f, f1.w * 8.f);
            uint32_t p2 = pack_f8x4(f2.x * 8.f, f2.y * 8.f, f2.z * 8.f, f2.w * 8.f);
            uint32_t p3 = pack_f8x4(f3.x * 8.f, f3.y * 8.f, f3.z * 8.f, f3.w * 8.f);
            const int kc = col >> 6, j = (col & 63) >> 4;
            uint32_t dst = sb + kc * 4096 + swz((uint32_t)r, (uint32_t)j);
            asm volatile("st.shared.v4.b32 [%0], {%1, %2, %3, %4};"
                         :: "r"(dst), "r"(p0), "r"(p1), "r"(p2), "r"(p3));
        }
        s += __shfl_xor_sync(0xFFFFFFFFu, s, 1);
        s += __shfl_xor_sync(0xFFFFFFFFu, s, 2);
        if (tid4 == 0) xsq_s[r] = s;
    }
    __syncthreads();

    // this thread's row squared-norms (pre-add the "1 +" of q's denominator)
    const int er0 = wm * 32 + group;
    float xs[2][2];
    #pragma unroll
    for (int mi = 0; mi < 2; ++mi) {
        xs[mi][0] = 1.f + xsq_s[er0 + mi * 16];
        xs[mi][1] = 1.f + xsq_s[er0 + mi * 16 + 8];
    }

    // ---- ldmatrix lane offsets ----
    uint32_t aAddr[2][2];
    {
        int r8   = (l & 7) + (((l >> 3) & 1) << 3);
        int cbit = l >> 4;
        #pragma unroll
        for (int mi = 0; mi < 2; ++mi) {
            int row = wm * 32 + mi * 16 + r8;
            aAddr[mi][0] = swz(row, cbit);
            aAddr[mi][1] = swz(row, 2 + cbit);
        }
    }
    uint32_t bAddr[2][2];
    {
        int m = l >> 3;
        #pragma unroll
        for (int p = 0; p < 2; ++p) {
            int row = wn * 32 + (p * 2 + (m >> 1)) * 8 + (l & 7);
            #pragma unroll
            for (int ks = 0; ks < 2; ++ks)
                bAddr[p][ks] = swz(row, 2 * ks + (m & 1));
        }
    }

    // fp16 accumulators: 2 regs per (mi,nj) fragment
    uint32_t acc[2][4][2];
    #pragma unroll
    for (int mi = 0; mi < 2; ++mi)
        #pragma unroll
        for (int nj = 0; nj < 4; ++nj) { acc[mi][nj][0] = 0u; acc[mi][nj][1] = 0u; }

    float rs[2][2] = {{0.f, 0.f}, {0.f, 0.f}};   // running row sums

    // ---- 8 N-tiles x 4 K-windows of 128; slot = idx&1 = kcp&1 ----
    #pragma unroll 1
    for (int nt = 0; nt < 8; ++nt) {
        #pragma unroll
        for (int kcp = 0; kcp < 4; ++kcp) {
            const int idx = nt * 4 + kcp;
            if (kcp == 0 && nt == 0) { CP_WAIT_1(); }   // stage 1 may keep flying
            else                     { CP_WAIT_0(); }
            __syncthreads();
            if (idx >= 1 && idx + 1 < 32) load_B(idx + 1, (kcp + 1) & 1);
            CP_COMMIT();

            const uint32_t stg = sb + B_OFF + (kcp & 1) * B_STAGE;
            #pragma unroll
            for (int half = 0; half < 2; ++half) {
                const uint32_t sA = sb + (kcp * 2 + half) * 4096;
                const uint32_t sB = stg + half * 8192;
                #pragma unroll
                for (int ks = 0; ks < 2; ++ks) {
                    uint32_t a[2][4], b[4][2];
                    #pragma unroll
                    for (int mi = 0; mi < 2; ++mi)
                        LDSM_X4(a[mi][0], a[mi][1], a[mi][2], a[mi][3], sA + aAddr[mi][ks]);
                    #pragma unroll
                    for (int p = 0; p < 2; ++p)
                        LDSM_X4(b[2*p][0], b[2*p][1], b[2*p+1][0], b[2*p+1][1],
                                sB + bAddr[p][ks]);
                    #pragma unroll
                    for (int mi = 0; mi < 2; ++mi)
                        #pragma unroll
                        for (int nj = 0; nj < 4; ++nj)
                            MMA_FP8H(acc[mi][nj][0], acc[mi][nj][1],
                                     a[mi][0], a[mi][1], a[mi][2], a[mi][3],
                                     b[nj][0], b[nj][1]);
                }
            }
        }

        // ---- N-tile epilogue (unpack f16 acc; csq via __ldg) ----
        {
            const int ntbase = nt * 128;
            const float kk = 1.f / 256.f;   // 2*cross = acc/256
            #pragma unroll
            for (int mi = 0; mi < 2; ++mi) {
                const int r0 = wm * 32 + mi * 16 + group;
                float* o0 = out + (size_t)(rowbase + r0) * KCL;
                float* o1 = out + (size_t)(rowbase + r0 + 8) * KCL;
                #pragma unroll
                for (int nj = 0; nj < 4; ++nj) {
                    const int colg = ntbase + wn * 32 + nj * 8 + tid4 * 2;
                    const float cs0 = __ldg(g_csq + colg);
                    const float cs1 = __ldg(g_csq + colg + 1);
                    float2 f0 = __half22float2(*reinterpret_cast<__half2*>(&acc[mi][nj][0]));
                    float2 f1 = __half22float2(*reinterpret_cast<__half2*>(&acc[mi][nj][1]));
                    acc[mi][nj][0] = 0u; acc[mi][nj][1] = 0u;
                    float q00 = __fdividef(1.f, fmaxf(xs[mi][0] + cs0 - kk * f0.x, 1.f));
                    float q01 = __fdividef(1.f, fmaxf(xs[mi][0] + cs1 - kk * f0.y, 1.f));
                    float q10 = __fdividef(1.f, fmaxf(xs[mi][1] + cs0 - kk * f1.x, 1.f));
                    float q11 = __fdividef(1.f, fmaxf(xs[mi][1] + cs1 - kk * f1.y, 1.f));
                    rs[mi][0] += q00 + q01;
                    rs[mi][1] += q10 + q11;
                    *reinterpret_cast<float2*>(o0 + colg) = make_float2(q00, q01);
                    *reinterpret_cast<float2*>(o1 + colg) = make_float2(q10, q11);
                }
            }
        }
    }

    // ---- final row-sum reduction (ps/rsum alias the dead B ring) ----
    CP_WAIT_0();
    __syncthreads();
    float* ps     = reinterpret_cast<float*>(smem + PS_OFF);   // [64][4]
    float* rsum_s = reinterpret_cast<float*>(smem + RSUM_OFF); // [64]
    #pragma unroll
    for (int mi = 0; mi < 2; ++mi) {
        float s0 = rs[mi][0], s1 = rs[mi][1];
        s0 += __shfl_xor_sync(0xFFFFFFFFu, s0, 1);
        s0 += __shfl_xor_sync(0xFFFFFFFFu, s0, 2);
        s1 += __shfl_xor_sync(0xFFFFFFFFu, s1, 1);
        s1 += __shfl_xor_sync(0xFFFFFFFFu, s1, 2);
        if (tid4 == 0) {
            const int r0 = wm * 32 + mi * 16 + group;
            ps[r0 * 4 + wn] = s0;
            ps[(r0 + 8) * 4 + wn] = s1;
        }
    }
    __syncthreads();
    if (t < 64)
        rsum_s[t] = __fdividef(1.f, ps[t * 4 + 0] + ps[t * 4 + 1] +
                                    ps[t * 4 + 2] + ps[t * 4 + 3]);
    __syncthreads();

    // ---- fused renormalization (256KB output slab, L2-resident) ----
    float4* op = reinterpret_cast<float4*>(out + (size_t)rowbase * KCL);
    #pragma unroll 4
    for (int r = 0; r < 64; ++r) {
        float iv = rsum_s[r];
        float4 v = op[(size_t)r * 256 + t];
        v.x *= iv; v.y *= iv; v.z *= iv; v.w *= iv;
        op[(size_t)r * 256 + t] = v;
    }
}

// ============================ launch =======================================
extern "C" void kernel_launch(void* const* d_in, const int* in_sizes, int n_in,
                              void* d_out, int out_size) {
    const float* x  = (const float*)d_in[0];   // (65536, 512)
    const float* cl = (const float*)d_in[1];   // (1024, 512)
    float* out = (float*)d_out;                // (65536, 1024)
    (void)in_sizes; (void)n_in; (void)out_size;

    cudaFuncSetAttribute(cluster_main_kernel,
                         cudaFuncAttributeMaxDynamicSharedMemorySize, SMEM_TOTAL);

    prep_clusters<<<KCL, 128>>>(cl);
    cluster_main_kernel<<<NROWS / 64, 256, SMEM_TOTAL>>>(x, out);
}